// round 5
// baseline (speedup 1.0000x reference)
#include <cuda_runtime.h>
#include <math.h>

// Problem dims
#define BSZ 2
#define SEQ 512
#define HID 1024
#define NHD 16
#define HDD 64
#define NL  4
#define FFD 4096
#define NCL 14
#define TOK (BSZ*SEQ)          // 1024
#define SHs (SEQ*HID)          // 524288   per-batch stride in q/k/v/x
#define HSC (SEQ*SEQ)          // 262144   per-head stride in score buffers
#define ZSC (NHD*SEQ*SEQ)      // 4194304  per-batch stride in score buffers

// ---------------- scratch (device globals: no cudaMalloc allowed) -------------
__device__ float g_x[TOK*HID];
__device__ float g_q[TOK*HID];
__device__ float g_k[TOK*HID];
__device__ float g_v[TOK*HID];
__device__ float g_rel[SEQ*HID];
__device__ float g_pk[SEQ*HID];
__device__ float g_pq[SEQ*HID];
__device__ float g_sc[BSZ*NHD*SEQ*SEQ];
__device__ float g_c2p[BSZ*NHD*SEQ*SEQ];
__device__ float g_p2c[BSZ*NHD*SEQ*SEQ];
__device__ float g_ctx[TOK*HID];
__device__ float g_ff[TOK*FFD];
__device__ int   g_idxm[SEQ*SEQ];
__device__ float g_nll[TOK];

// ---------------- block reduction helper (blockDim.x multiple of 32) ----------
__device__ __forceinline__ float blk_sum(float v, float* red) {
    #pragma unroll
    for (int o = 16; o; o >>= 1) v += __shfl_down_sync(0xffffffffu, v, o);
    int w = threadIdx.x >> 5, lane = threadIdx.x & 31;
    int nw = blockDim.x >> 5;
    __syncthreads();                 // guard red reuse
    if (lane == 0) red[w] = v;
    __syncthreads();
    if (threadIdx.x == 0) { float s = 0.f; for (int i = 0; i < nw; i++) s += red[i]; red[0] = s; }
    __syncthreads();
    return red[0];
}

// ---------------- tf32 helpers ------------------------------------------------
__device__ __forceinline__ void split_tf32(float x, float& h, float& l) {
    unsigned u; asm("cvt.rna.tf32.f32 %0, %1;" : "=r"(u) : "f"(x));
    h = __uint_as_float(u);
    float r = x - h;
    unsigned v2; asm("cvt.rna.tf32.f32 %0, %1;" : "=r"(v2) : "f"(r));
    l = __uint_as_float(v2);
}

__device__ __forceinline__ void mma_tf32(float* d, const float* a, const float* b) {
    asm volatile(
        "mma.sync.aligned.m16n8k8.row.col.f32.tf32.tf32.f32 "
        "{%0,%1,%2,%3}, {%4,%5,%6,%7}, {%8,%9}, {%0,%1,%2,%3};\n"
        : "+f"(d[0]), "+f"(d[1]), "+f"(d[2]), "+f"(d[3])
        : "r"(__float_as_uint(a[0])), "r"(__float_as_uint(a[1])),
          "r"(__float_as_uint(a[2])), "r"(__float_as_uint(a[3])),
          "r"(__float_as_uint(b[0])), "r"(__float_as_uint(b[1])));
}

// ---------------- tensor-core GEMM (3xTF32): C = act(A @ op(B) + bias) --------
// Block tile 128(M) x 64(N), BK=16, 256 threads (8 warps, 4x2), warp tile 32x32.
// TB=true -> B given as [N,K] row-major (computes A @ B^T).
// Smem row stride 20 (== 4 mod 32) makes fragment LDS conflict-free.
template<int ACT, bool TB>
__global__ __launch_bounds__(256)
void tgemm_k(const float* __restrict__ A, const float* __restrict__ Bm,
             float* __restrict__ C, const float* __restrict__ bias,
             int K, int lda, int ldb, int ldc,
             long aB, long aH, long bB, long bH, long cB, long cH, int nh)
{
    int z = blockIdx.z;
    int zb = z / nh, zh = z - zb * nh;
    A  += zb * aB + zh * aH;
    Bm += zb * bB + zh * bH;
    C  += zb * cB + zh * cH;

    __shared__ float Ah[128][20], Al[128][20];   // [m][k]
    __shared__ float Bh[64][20],  Bl[64][20];    // [n][k]

    const int tid  = threadIdx.x;
    const int warp = tid >> 5, lane = tid & 31;
    const int wm = warp >> 1;          // 0..3
    const int wn = warp & 1;           // 0..1
    const int m0 = blockIdx.y << 7;
    const int n0 = blockIdx.x << 6;
    const int g  = lane >> 2;          // 0..7
    const int t  = lane & 3;           // 0..3

    float acc[2][4][4];
    #pragma unroll
    for (int i = 0; i < 2; i++)
        #pragma unroll
        for (int j = 0; j < 4; j++)
            #pragma unroll
            for (int c = 0; c < 4; c++) acc[i][j][c] = 0.f;

    // global->smem load indices
    const int ar = tid >> 1;                 // 0..127
    const int ac = (tid & 1) << 3;           // 0 or 8
    const int brn = tid >> 2;                // 0..63   (TB)
    const int bck = (tid & 3) << 2;          // 0,4,8,12
    const int brk = tid >> 4;                // 0..15   (!TB)
    const int bcn = (tid & 15) << 2;         // 0..60

    for (int k0 = 0; k0 < K; k0 += 16) {
        // ---- A tile 128x16 ----
        const float* Ap = A + (long)(m0 + ar) * lda + k0 + ac;
        #pragma unroll
        for (int j = 0; j < 8; j += 4) {
            float4 v = *(const float4*)(Ap + j);
            float4 h, l;
            split_tf32(v.x, h.x, l.x); split_tf32(v.y, h.y, l.y);
            split_tf32(v.z, h.z, l.z); split_tf32(v.w, h.w, l.w);
            *(float4*)&Ah[ar][ac + j] = h;
            *(float4*)&Al[ar][ac + j] = l;
        }
        // ---- B tile -> Bs[n][k] ----
        if (TB) {
            float4 v = *(const float4*)(Bm + (long)(n0 + brn) * ldb + k0 + bck);
            float4 h, l;
            split_tf32(v.x, h.x, l.x); split_tf32(v.y, h.y, l.y);
            split_tf32(v.z, h.z, l.z); split_tf32(v.w, h.w, l.w);
            *(float4*)&Bh[brn][bck] = h;
            *(float4*)&Bl[brn][bck] = l;
        } else {
            float4 v = *(const float4*)(Bm + (long)(k0 + brk) * ldb + n0 + bcn);
            float h0, l0;
            split_tf32(v.x, h0, l0); Bh[bcn+0][brk] = h0; Bl[bcn+0][brk] = l0;
            split_tf32(v.y, h0, l0); Bh[bcn+1][brk] = h0; Bl[bcn+1][brk] = l0;
            split_tf32(v.z, h0, l0); Bh[bcn+2][brk] = h0; Bl[bcn+2][brk] = l0;
            split_tf32(v.w, h0, l0); Bh[bcn+3][brk] = h0; Bl[bcn+3][brk] = l0;
        }
        __syncthreads();

        #pragma unroll
        for (int ks = 0; ks < 16; ks += 8) {
            float ah[2][4], al[2][4];
            #pragma unroll
            for (int mt = 0; mt < 2; mt++) {
                int mr = (wm << 5) + (mt << 4);
                ah[mt][0] = Ah[mr + g][ks + t];
                ah[mt][1] = Ah[mr + g + 8][ks + t];
                ah[mt][2] = Ah[mr + g][ks + t + 4];
                ah[mt][3] = Ah[mr + g + 8][ks + t + 4];
                al[mt][0] = Al[mr + g][ks + t];
                al[mt][1] = Al[mr + g + 8][ks + t];
                al[mt][2] = Al[mr + g][ks + t + 4];
                al[mt][3] = Al[mr + g + 8][ks + t + 4];
            }
            #pragma unroll
            for (int nt = 0; nt < 4; nt++) {
                int nc = (wn << 5) + (nt << 3) + g;
                float bh[2], bl[2];
                bh[0] = Bh[nc][ks + t];
                bh[1] = Bh[nc][ks + t + 4];
                bl[0] = Bl[nc][ks + t];
                bl[1] = Bl[nc][ks + t + 4];
                mma_tf32(acc[0][nt], ah[0], bh);
                mma_tf32(acc[1][nt], ah[1], bh);
                mma_tf32(acc[0][nt], ah[0], bl);
                mma_tf32(acc[1][nt], ah[1], bl);
                mma_tf32(acc[0][nt], al[0], bh);
                mma_tf32(acc[1][nt], al[1], bh);
            }
        }
        __syncthreads();
    }

    // epilogue
    #pragma unroll
    for (int mt = 0; mt < 2; mt++) {
        #pragma unroll
        for (int nt = 0; nt < 4; nt++) {
            int col = n0 + (wn << 5) + (nt << 3) + (t << 1);
            float b0 = bias ? bias[col]     : 0.f;
            float b1 = bias ? bias[col + 1] : 0.f;
            #pragma unroll
            for (int half = 0; half < 2; half++) {
                int row = m0 + (wm << 5) + (mt << 4) + g + (half << 3);
                float v0 = acc[mt][nt][half * 2 + 0] + b0;
                float v1 = acc[mt][nt][half * 2 + 1] + b1;
                if (ACT == 1) {
                    v0 = 0.5f * v0 * (1.0f + erff(v0 * 0.70710678118654752f));
                    v1 = 0.5f * v1 * (1.0f + erff(v1 * 0.70710678118654752f));
                }
                *(float2*)(C + (long)row * ldc + col) = make_float2(v0, v1);
            }
        }
    }
}

// ---------------- embedding: x = LN(word_emb[id]) * maskf ---------------------
__global__ void embed_ln_k(const float* __restrict__ emb,
                           const float* __restrict__ s, const float* __restrict__ b,
                           const int* __restrict__ ids, const int* __restrict__ am,
                           float* __restrict__ out)
{
    __shared__ float sh[HID];
    __shared__ float red[8];
    int tok = blockIdx.x;
    long ebase = (long)ids[tok] * HID;
    float m = (float)am[tok];
    float ls = 0.f;
    for (int i = threadIdx.x; i < HID; i += blockDim.x) { float v = emb[ebase + i]; sh[i] = v; ls += v; }
    __syncthreads();
    float mu = blk_sum(ls, red) * (1.0f / HID);
    float lv = 0.f;
    for (int i = threadIdx.x; i < HID; i += blockDim.x) { float d = sh[i] - mu; lv += d * d; }
    float var = blk_sum(lv, red) * (1.0f / HID);
    float r = rsqrtf(var + 1e-7f);
    long obase = (long)tok * HID;
    for (int i = threadIdx.x; i < HID; i += blockDim.x)
        out[obase + i] = ((sh[i] - mu) * r * s[i] + b[i]) * m;
}

// ---------------- residual + LN: out = LN((res?) + t) -------------------------
__global__ void add_ln_k(const float* res, const float* __restrict__ t,
                         const float* __restrict__ s, const float* __restrict__ b,
                         float* out)
{
    __shared__ float sh[HID];
    __shared__ float red[8];
    long base = (long)blockIdx.x * HID;
    float ls = 0.f;
    for (int i = threadIdx.x; i < HID; i += blockDim.x) {
        float v = t[base + i];
        if (res) v += res[base + i];
        sh[i] = v; ls += v;
    }
    __syncthreads();
    float mu = blk_sum(ls, red) * (1.0f / HID);
    float lv = 0.f;
    for (int i = threadIdx.x; i < HID; i += blockDim.x) { float d = sh[i] - mu; lv += d * d; }
    float var = blk_sum(lv, red) * (1.0f / HID);
    float r = rsqrtf(var + 1e-7f);
    for (int i = threadIdx.x; i < HID; i += blockDim.x)
        out[base + i] = (sh[i] - mu) * r * s[i] + b[i];
}

// ---------------- DeBERTa log-bucket relative index ---------------------------
__global__ void build_idx_k(int* __restrict__ idxm)
{
    int q = blockIdx.x;
    const int mid = 128;
    for (int k = threadIdx.x; k < SEQ; k += blockDim.x) {
        int rel = q - k;
        int a = (rel < mid && rel > -mid) ? (mid - 1) : (rel < 0 ? -rel : rel);
        int bucket;
        if (a <= mid) bucket = rel;
        else {
            float lp = ceilf(logf((float)a / (float)mid) / logf(511.0f / (float)mid) * (float)(mid - 1))
                       + (float)mid;
            float sgn = (rel > 0) ? 1.f : ((rel < 0) ? -1.f : 0.f);
            bucket = (int)(lp * sgn);
        }
        int J = bucket + 256;
        J = J < 0 ? 0 : (J > 511 ? 511 : J);
        idxm[q * SEQ + k] = J;
    }
}

// ------- combine + mask + softmax:  probs = softmax((qk + c2p[J] + p2c[J])/scale)
__global__ void attn_softmax_k(float* __restrict__ sc, const float* __restrict__ c2p,
                               const float* __restrict__ p2c, const int* __restrict__ idxm,
                               const int* __restrict__ am)
{
    __shared__ float red[4];
    int q = blockIdx.x, z = blockIdx.y;
    int b = z >> 4;                     // NHD = 16
    long ro = ((long)z * SEQ + q) * (long)SEQ;
    float* row = sc + ro;
    const float* cr = c2p + ro;
    const float* pb = p2c + (long)z * SEQ * 512;
    int mq = am[b * SEQ + q];
    const float scale = sqrtf(3.0f * (float)HDD);
    float vals[4]; int msk[4];
    float mx = -3.402823466e38f;
    #pragma unroll
    for (int t = 0; t < 4; t++) {
        int k = threadIdx.x + t * 128;
        int J = idxm[q * SEQ + k];
        float v = (row[k] + cr[J] + pb[(long)k * 512 + J]) / scale;
        int mk = mq & am[b * SEQ + k];
        vals[t] = v; msk[t] = mk;
        if (mk) mx = fmaxf(mx, v);
    }
    #pragma unroll
    for (int o = 16; o; o >>= 1) mx = fmaxf(mx, __shfl_down_sync(0xffffffffu, mx, o));
    if ((threadIdx.x & 31) == 0) red[threadIdx.x >> 5] = mx;
    __syncthreads();
    mx = fmaxf(fmaxf(red[0], red[1]), fmaxf(red[2], red[3]));
    float ls = 0.f;
    #pragma unroll
    for (int t = 0; t < 4; t++) {
        float e = msk[t] ? expf(vals[t] - mx) : 0.f;
        vals[t] = e; ls += e;
    }
    __syncthreads();
    #pragma unroll
    for (int o = 16; o; o >>= 1) ls += __shfl_down_sync(0xffffffffu, ls, o);
    if ((threadIdx.x & 31) == 0) red[threadIdx.x >> 5] = ls;
    __syncthreads();
    float sum = red[0] + red[1] + red[2] + red[3];
    float inv = sum > 0.f ? 1.0f / sum : 0.f;
    #pragma unroll
    for (int t = 0; t < 4; t++) row[threadIdx.x + t * 128] = vals[t] * inv;
}

// ---------------- decoder (N=14) + per-row masked NLL -------------------------
__global__ void decoder_k(const float* __restrict__ t, const float* __restrict__ Wd,
                          const float* __restrict__ bd, const int* __restrict__ labels,
                          const int* __restrict__ am, float* __restrict__ out,
                          int logit_limit, float* __restrict__ nll)
{
    __shared__ float sh[HID];
    __shared__ float wred[4][NCL];
    __shared__ float lg[NCL];
    int row = blockIdx.x;
    long base = (long)row * HID;
    for (int i = threadIdx.x; i < HID; i += 128) sh[i] = t[base + i];
    __syncthreads();
    float p[NCL];
    #pragma unroll
    for (int c = 0; c < NCL; c++) p[c] = 0.f;
    for (int i = threadIdx.x; i < HID; i += 128) {
        float tv = sh[i];
        const float* w = Wd + (long)i * NCL;
        #pragma unroll
        for (int c = 0; c < NCL; c++) p[c] = fmaf(tv, w[c], p[c]);
    }
    #pragma unroll
    for (int c = 0; c < NCL; c++)
        #pragma unroll
        for (int o = 16; o; o >>= 1) p[c] += __shfl_down_sync(0xffffffffu, p[c], o);
    if ((threadIdx.x & 31) == 0) {
        int w = threadIdx.x >> 5;
        #pragma unroll
        for (int c = 0; c < NCL; c++) wred[w][c] = p[c];
    }
    __syncthreads();
    if (threadIdx.x < NCL) {
        float v = wred[0][threadIdx.x] + wred[1][threadIdx.x]
                + wred[2][threadIdx.x] + wred[3][threadIdx.x] + bd[threadIdx.x];
        lg[threadIdx.x] = v;
        int oi = row * NCL + threadIdx.x;
        if (oi < logit_limit) out[oi] = v;
    }
    __syncthreads();
    if (threadIdx.x == 0) {
        float m = lg[0];
        #pragma unroll
        for (int c = 1; c < NCL; c++) m = fmaxf(m, lg[c]);
        float ssum = 0.f;
        #pragma unroll
        for (int c = 0; c < NCL; c++) ssum += expf(lg[c] - m);
        float lse = m + logf(ssum);
        float nl = lse - lg[labels[row]];
        nll[row] = nl * (float)am[row];
    }
}

__global__ void finalize_k(const float* __restrict__ nll, const int* __restrict__ am,
                           float* __restrict__ out, int loss_idx)
{
    __shared__ float red[8];
    float a = 0.f, bm = 0.f;
    for (int i = threadIdx.x; i < TOK; i += 256) { a += nll[i]; bm += (float)am[i]; }
    float sa = blk_sum(a, red);
    float sb = blk_sum(bm, red);
    if (threadIdx.x == 0 && loss_idx >= 0) out[loss_idx] = sa / fmaxf(sb, 1.0f);
}

// ------------------------------- host driver ----------------------------------
extern "C" void kernel_launch(void* const* d_in, const int* in_sizes, int n_in,
                              void* d_out, int out_size)
{
    (void)in_sizes; (void)n_in;
    const float* word_emb = (const float*)d_in[0];
    const float* emb_ln_s = (const float*)d_in[1];
    const float* emb_ln_b = (const float*)d_in[2];
    const float* rel_emb  = (const float*)d_in[3];
    const float* rel_ln_s = (const float*)d_in[4];
    const float* rel_ln_b = (const float*)d_in[5];
    const float* Wq = (const float*)d_in[6];
    const float* bq = (const float*)d_in[7];
    const float* Wk = (const float*)d_in[8];
    const float* bk = (const float*)d_in[9];
    const float* Wv = (const float*)d_in[10];
    const float* bv = (const float*)d_in[11];
    const float* Wo = (const float*)d_in[12];
    const float* bo = (const float*)d_in[13];
    const float* ln1_s = (const float*)d_in[14];
    const float* ln1_b = (const float*)d_in[15];
    const float* W1 = (const float*)d_in[16];
    const float* b1 = (const float*)d_in[17];
    const float* W2 = (const float*)d_in[18];
    const float* b2 = (const float*)d_in[19];
    const float* ln2_s = (const float*)d_in[20];
    const float* ln2_b = (const float*)d_in[21];
    const float* Wt = (const float*)d_in[22];
    const float* bt = (const float*)d_in[23];
    const float* tln_s = (const float*)d_in[24];
    const float* tln_b = (const float*)d_in[25];
    const float* Wd = (const float*)d_in[26];
    const float* bd = (const float*)d_in[27];
    const int* ids    = (const int*)d_in[28];
    const int* am     = (const int*)d_in[29];
    const int* labels = (const int*)d_in[30];
    float* out = (float*)d_out;

    float *x, *q, *k, *v, *rel, *pk, *pq, *sc, *c2p, *p2c, *ctx, *ff, *nll;
    int* idxm;
    cudaGetSymbolAddress((void**)&x,   g_x);
    cudaGetSymbolAddress((void**)&q,   g_q);
    cudaGetSymbolAddress((void**)&k,   g_k);
    cudaGetSymbolAddress((void**)&v,   g_v);
    cudaGetSymbolAddress((void**)&rel, g_rel);
    cudaGetSymbolAddress((void**)&pk,  g_pk);
    cudaGetSymbolAddress((void**)&pq,  g_pq);
    cudaGetSymbolAddress((void**)&sc,  g_sc);
    cudaGetSymbolAddress((void**)&c2p, g_c2p);
    cudaGetSymbolAddress((void**)&p2c, g_p2c);
    cudaGetSymbolAddress((void**)&ctx, g_ctx);
    cudaGetSymbolAddress((void**)&ff,  g_ff);
    cudaGetSymbolAddress((void**)&nll, g_nll);
    cudaGetSymbolAddress((void**)&idxm, g_idxm);

    build_idx_k<<<SEQ, 128>>>(idxm);
    embed_ln_k<<<TOK, 256>>>(word_emb, emb_ln_s, emb_ln_b, ids, am, x);
    add_ln_k<<<SEQ, 256>>>(nullptr, rel_emb, rel_ln_s, rel_ln_b, rel);

    const dim3 gProj(HID / 64, TOK / 128, 1);     // (16, 8)
    const dim3 gPos(HID / 64, SEQ / 128, 1);      // (16, 4)
    const dim3 gAtt(SEQ / 64, SEQ / 128, BSZ * NHD);  // (8, 4, 32)
    const dim3 gCtx(1, SEQ / 128, BSZ * NHD);     // (1, 4, 32)
    const dim3 gFF1(FFD / 64, TOK / 128, 1);      // (64, 8)

    for (int l = 0; l < NL; l++) {
        const float* Wq_l = Wq + (long)l * HID * HID;
        const float* Wk_l = Wk + (long)l * HID * HID;
        const float* Wv_l = Wv + (long)l * HID * HID;
        const float* Wo_l = Wo + (long)l * HID * HID;
        const float* bq_l = bq + l * HID;
        const float* bk_l = bk + l * HID;
        const float* bv_l = bv + l * HID;
        const float* bo_l = bo + l * HID;
        const float* W1_l = W1 + (long)l * HID * FFD;
        const float* b1_l = b1 + l * FFD;
        const float* W2_l = W2 + (long)l * FFD * HID;
        const float* b2_l = b2 + l * HID;

        // Q/K/V projections
        tgemm_k<0, false><<<gProj, 256>>>(x, Wq_l, q, bq_l, HID, HID, HID, HID, 0,0,0,0,0,0, 1);
        tgemm_k<0, false><<<gProj, 256>>>(x, Wk_l, k, bk_l, HID, HID, HID, HID, 0,0,0,0,0,0, 1);
        tgemm_k<0, false><<<gProj, 256>>>(x, Wv_l, v, bv_l, HID, HID, HID, HID, 0,0,0,0,0,0, 1);
        // positional keys/queries (share_att_key): rel_ln @ Wk/Wq + bias
        tgemm_k<0, false><<<gPos, 256>>>(rel, Wk_l, pk, bk_l, HID, HID, HID, HID, 0,0,0,0,0,0, 1);
        tgemm_k<0, false><<<gPos, 256>>>(rel, Wq_l, pq, bq_l, HID, HID, HID, HID, 0,0,0,0,0,0, 1);
        // attention GEMMs (A @ B^T per (b,h)): qk, c2p, p2c
        tgemm_k<0, true><<<gAtt, 256>>>(q, k,  sc,  nullptr, HDD, HID, HID, SEQ,
                                        SHs, HDD, SHs, HDD, ZSC, HSC, NHD);
        tgemm_k<0, true><<<gAtt, 256>>>(q, pk, c2p, nullptr, HDD, HID, HID, 512,
                                        SHs, HDD, 0,   HDD, ZSC, HSC, NHD);
        tgemm_k<0, true><<<gAtt, 256>>>(k, pq, p2c, nullptr, HDD, HID, HID, 512,
                                        SHs, HDD, 0,   HDD, ZSC, HSC, NHD);
        // combine disentangled biases + mask + softmax (in-place -> probs)
        attn_softmax_k<<<dim3(SEQ, BSZ * NHD), 128>>>(sc, c2p, p2c, idxm, am);
        // ctx = probs @ V
        tgemm_k<0, false><<<gCtx, 256>>>(sc, v, ctx, nullptr, SEQ, SEQ, HID, HID,
                                         ZSC, HSC, SHs, HDD, SHs, HDD, NHD);
        // output proj + residual LN
        tgemm_k<0, false><<<gProj, 256>>>(ctx, Wo_l, ff, bo_l, HID, HID, HID, HID, 0,0,0,0,0,0, 1);
        add_ln_k<<<TOK, 256>>>(x, ff, ln1_s + l * HID, ln1_b + l * HID, x);
        // FFN
        tgemm_k<1, false><<<gFF1, 256>>>(x, W1_l, ff, b1_l, HID, HID, FFD, FFD, 0,0,0,0,0,0, 1);
        tgemm_k<0, false><<<gProj, 256>>>(ff, W2_l, ctx, b2_l, FFD, FFD, HID, HID, 0,0,0,0,0,0, 1);
        add_ln_k<<<TOK, 256>>>(x, ctx, ln2_s + l * HID, ln2_b + l * HID, x);
    }

    // transform head: LN(gelu(x @ Wt + bt))
    tgemm_k<1, false><<<gProj, 256>>>(x, Wt, ff, bt, HID, HID, HID, HID, 0,0,0,0,0,0, 1);
    add_ln_k<<<TOK, 256>>>(nullptr, ff, tln_s, tln_b, q);   // reuse q buffer as t

    int logits_n = TOK * NCL;                               // 14336
    int logit_limit = (out_size > 1) ? (out_size < logits_n ? out_size : logits_n) : 0;
    int loss_idx = (out_size == 1) ? 0 : (out_size > logits_n ? logits_n : -1);
    decoder_k<<<TOK, 128>>>(q, Wd, bd, labels, am, out, logit_limit, nll);
    finalize_k<<<1, 256>>>(nll, am, out, loss_idx);
}

// round 6
// speedup vs baseline: 1.3091x; 1.3091x over previous
#include <cuda_runtime.h>
#include <math.h>

// Problem dims
#define BSZ 2
#define SEQ 512
#define HID 1024
#define NHD 16
#define HDD 64
#define NL  4
#define FFD 4096
#define NCL 14
#define TOK (BSZ*SEQ)          // 1024
#define SHs (SEQ*HID)          // 524288   per-batch stride in q/k/v/x
#define HSC (SEQ*SEQ)          // 262144   per-head stride in score buffers
#define ZSC (NHD*SEQ*SEQ)      // 4194304  per-batch stride in score buffers

// ---------------- scratch (device globals: no cudaMalloc allowed) -------------
__device__ float g_x[TOK*HID];
__device__ float g_q[TOK*HID];
__device__ float g_k[TOK*HID];
__device__ float g_v[TOK*HID];
__device__ float g_rel[SEQ*HID];
__device__ float g_pk[SEQ*HID];
__device__ float g_pq[SEQ*HID];
__device__ float g_sc[BSZ*NHD*SEQ*SEQ];
__device__ float g_c2p[BSZ*NHD*SEQ*SEQ];
__device__ float g_p2c[BSZ*NHD*SEQ*SEQ];
__device__ float g_ctx[TOK*HID];
__device__ float g_ff[TOK*FFD];
__device__ int   g_idxm[SEQ*SEQ];
__device__ float g_nll[TOK];

// ---------------- job descriptors (passed in kernel params) -------------------
struct JobDesc { const float* A; const float* B; float* C; const float* bias; int M; int pad; };
template<int NJ> struct JobsP { JobDesc j[NJ]; };

// ---------------- block reduction helper --------------------------------------
__device__ __forceinline__ float blk_sum(float v, float* red) {
    #pragma unroll
    for (int o = 16; o; o >>= 1) v += __shfl_down_sync(0xffffffffu, v, o);
    int w = threadIdx.x >> 5, lane = threadIdx.x & 31;
    int nw = blockDim.x >> 5;
    __syncthreads();
    if (lane == 0) red[w] = v;
    __syncthreads();
    if (threadIdx.x == 0) { float s = 0.f; for (int i = 0; i < nw; i++) s += red[i]; red[0] = s; }
    __syncthreads();
    return red[0];
}

// ---------------- tf32 helpers ------------------------------------------------
__device__ __forceinline__ void split_tf32(float x, float& h, float& l) {
    unsigned u; asm("cvt.rna.tf32.f32 %0, %1;" : "=r"(u) : "f"(x));
    h = __uint_as_float(u);
    float r = x - h;
    unsigned v2; asm("cvt.rna.tf32.f32 %0, %1;" : "=r"(v2) : "f"(r));
    l = __uint_as_float(v2);
}

__device__ __forceinline__ void mma_tf32(float* d, const float* a, const float* b) {
    asm volatile(
        "mma.sync.aligned.m16n8k8.row.col.f32.tf32.tf32.f32 "
        "{%0,%1,%2,%3}, {%4,%5,%6,%7}, {%8,%9}, {%0,%1,%2,%3};\n"
        : "+f"(d[0]), "+f"(d[1]), "+f"(d[2]), "+f"(d[3])
        : "r"(__float_as_uint(a[0])), "r"(__float_as_uint(a[1])),
          "r"(__float_as_uint(a[2])), "r"(__float_as_uint(a[3])),
          "r"(__float_as_uint(b[0])), "r"(__float_as_uint(b[1])));
}

#define SMEM_BYTES ((2*128*20*2 + 2*64*20*2) * 4)   // 61440

// ---------------- tensor-core GEMM (3xTF32, double-buffered, job table) -------
// Block tile 128(M) x 64(N), BK=16, 256 threads (8 warps 4x2), warp tile 32x32.
// TB=true -> B given as [N,K] row-major (computes A @ B^T).
// 2-stage smem pipeline with register staging; MMAs grouped by compensation
// term for dependency distance 8.
template<int ACT, bool TB, int NJ>
__global__ __launch_bounds__(256)
void tgemm_k(JobsP<NJ> P, int K, int lda, int ldb, int ldc)
{
    const JobDesc jd = P.j[blockIdx.z];
    const int m0 = blockIdx.y << 7;
    if (m0 >= jd.M) return;
    const float* __restrict__ A  = jd.A;
    const float* __restrict__ Bm = jd.B;
    float* __restrict__ C = jd.C;
    const float* bias = jd.bias;
    const int n0 = blockIdx.x << 6;

    extern __shared__ float smem_[];
    float* AhS = smem_;                       // [2][128][20]
    float* AlS = AhS + 2*128*20;
    float* BhS = AlS + 2*128*20;              // [2][64][20]
    float* BlS = BhS + 2*64*20;

    const int tid  = threadIdx.x;
    const int warp = tid >> 5, lane = tid & 31;
    const int wm = warp >> 1;          // 0..3
    const int wn = warp & 1;           // 0..1
    const int g  = lane >> 2;          // 0..7
    const int t  = lane & 3;           // 0..3

    const int ar  = tid >> 1;                // 0..127
    const int ac  = (tid & 1) << 3;          // 0 or 8
    const int brn = tid >> 2;                // 0..63   (TB)
    const int bck = (tid & 3) << 2;          // 0,4,8,12
    const int brk = tid >> 4;                // 0..15   (!TB)
    const int bcn = (tid & 15) << 2;         // 0..60

    float acc[2][4][4] = {};
    float4 ra0, ra1, rbv;

    // ---- prologue: load k-tile 0 into regs, split+store to stage 0 ----
    {
        const float* Ap = A + (long)(m0 + ar) * lda + ac;
        ra0 = *(const float4*)Ap; ra1 = *(const float4*)(Ap + 4);
        if (TB) rbv = *(const float4*)(Bm + (long)(n0 + brn) * ldb + bck);
        else    rbv = *(const float4*)(Bm + (long)brk * ldb + n0 + bcn);
    }
    {
        float* dh = AhS + (long)ar * 20 + ac;
        float* dl = AlS + (long)ar * 20 + ac;
        float hv[8] = {ra0.x,ra0.y,ra0.z,ra0.w, ra1.x,ra1.y,ra1.z,ra1.w};
        #pragma unroll
        for (int i = 0; i < 8; i++) { float h,l; split_tf32(hv[i],h,l); dh[i]=h; dl[i]=l; }
        float bv[4] = {rbv.x,rbv.y,rbv.z,rbv.w};
        if (TB) {
            float* eh = BhS + (long)brn * 20 + bck;
            float* el = BlS + (long)brn * 20 + bck;
            #pragma unroll
            for (int i = 0; i < 4; i++) { float h,l; split_tf32(bv[i],h,l); eh[i]=h; el[i]=l; }
        } else {
            #pragma unroll
            for (int i = 0; i < 4; i++) { float h,l; split_tf32(bv[i],h,l);
                BhS[(long)(bcn+i)*20 + brk] = h; BlS[(long)(bcn+i)*20 + brk] = l; }
        }
    }
    __syncthreads();

    const int KT = K >> 4;
    for (int kt = 0; kt < KT; kt++) {
        const int st = kt & 1;
        const bool more = (kt + 1 < KT);
        if (more) {
            int k0 = (kt + 1) << 4;
            const float* Ap = A + (long)(m0 + ar) * lda + k0 + ac;
            ra0 = *(const float4*)Ap; ra1 = *(const float4*)(Ap + 4);
            if (TB) rbv = *(const float4*)(Bm + (long)(n0 + brn) * ldb + k0 + bck);
            else    rbv = *(const float4*)(Bm + (long)(k0 + brk) * ldb + n0 + bcn);
        }
        const float* pAh = AhS + st * 128 * 20;
        const float* pAl = AlS + st * 128 * 20;
        const float* pBh = BhS + st * 64 * 20;
        const float* pBl = BlS + st * 64 * 20;
        #pragma unroll
        for (int ks = 0; ks < 16; ks += 8) {
            float ah[2][4], al[2][4], bh[4][2], bl[4][2];
            #pragma unroll
            for (int mt = 0; mt < 2; mt++) {
                int mr = (wm << 5) + (mt << 4);
                ah[mt][0] = pAh[(mr+g)*20 + ks+t];
                ah[mt][1] = pAh[(mr+g+8)*20 + ks+t];
                ah[mt][2] = pAh[(mr+g)*20 + ks+t+4];
                ah[mt][3] = pAh[(mr+g+8)*20 + ks+t+4];
                al[mt][0] = pAl[(mr+g)*20 + ks+t];
                al[mt][1] = pAl[(mr+g+8)*20 + ks+t];
                al[mt][2] = pAl[(mr+g)*20 + ks+t+4];
                al[mt][3] = pAl[(mr+g+8)*20 + ks+t+4];
            }
            #pragma unroll
            for (int nt = 0; nt < 4; nt++) {
                int nc = (wn << 5) + (nt << 3) + g;
                bh[nt][0] = pBh[nc*20 + ks+t];
                bh[nt][1] = pBh[nc*20 + ks+t+4];
                bl[nt][0] = pBl[nc*20 + ks+t];
                bl[nt][1] = pBl[nc*20 + ks+t+4];
            }
            #pragma unroll
            for (int mt = 0; mt < 2; mt++)
                #pragma unroll
                for (int nt = 0; nt < 4; nt++) mma_tf32(acc[mt][nt], ah[mt], bh[nt]);
            #pragma unroll
            for (int mt = 0; mt < 2; mt++)
                #pragma unroll
                for (int nt = 0; nt < 4; nt++) mma_tf32(acc[mt][nt], ah[mt], bl[nt]);
            #pragma unroll
            for (int mt = 0; mt < 2; mt++)
                #pragma unroll
                for (int nt = 0; nt < 4; nt++) mma_tf32(acc[mt][nt], al[mt], bh[nt]);
        }
        if (more) {
            const int s2 = (kt + 1) & 1;
            float* dh = AhS + ((long)s2*128 + ar)*20 + ac;
            float* dl = AlS + ((long)s2*128 + ar)*20 + ac;
            float hv[8] = {ra0.x,ra0.y,ra0.z,ra0.w, ra1.x,ra1.y,ra1.z,ra1.w};
            #pragma unroll
            for (int i = 0; i < 8; i++) { float h,l; split_tf32(hv[i],h,l); dh[i]=h; dl[i]=l; }
            float bv[4] = {rbv.x,rbv.y,rbv.z,rbv.w};
            if (TB) {
                float* eh = BhS + ((long)s2*64 + brn)*20 + bck;
                float* el = BlS + ((long)s2*64 + brn)*20 + bck;
                #pragma unroll
                for (int i = 0; i < 4; i++) { float h,l; split_tf32(bv[i],h,l); eh[i]=h; el[i]=l; }
            } else {
                #pragma unroll
                for (int i = 0; i < 4; i++) { float h,l; split_tf32(bv[i],h,l);
                    BhS[((long)s2*64 + bcn+i)*20 + brk] = h; BlS[((long)s2*64 + bcn+i)*20 + brk] = l; }
            }
        }
        __syncthreads();
    }

    // epilogue
    #pragma unroll
    for (int mt = 0; mt < 2; mt++) {
        #pragma unroll
        for (int nt = 0; nt < 4; nt++) {
            int col = n0 + (wn << 5) + (nt << 3) + (t << 1);
            float b0 = bias ? bias[col]     : 0.f;
            float b1 = bias ? bias[col + 1] : 0.f;
            #pragma unroll
            for (int half = 0; half < 2; half++) {
                int row = m0 + (wm << 5) + (mt << 4) + g + (half << 3);
                float v0 = acc[mt][nt][half * 2 + 0] + b0;
                float v1 = acc[mt][nt][half * 2 + 1] + b1;
                if (ACT == 1) {
                    v0 = 0.5f * v0 * (1.0f + erff(v0 * 0.70710678118654752f));
                    v1 = 0.5f * v1 * (1.0f + erff(v1 * 0.70710678118654752f));
                }
                *(float2*)(C + (long)row * ldc + col) = make_float2(v0, v1);
            }
        }
    }
}

// ---------------- embedding: x = LN(word_emb[id]) * maskf ---------------------
__global__ void embed_ln_k(const float* __restrict__ emb,
                           const float* __restrict__ s, const float* __restrict__ b,
                           const int* __restrict__ ids, const int* __restrict__ am,
                           float* __restrict__ out)
{
    __shared__ float sh[HID];
    __shared__ float red[8];
    int tok = blockIdx.x;
    long ebase = (long)ids[tok] * HID;
    float m = (float)am[tok];
    float ls = 0.f;
    for (int i = threadIdx.x; i < HID; i += blockDim.x) { float v = emb[ebase + i]; sh[i] = v; ls += v; }
    __syncthreads();
    float mu = blk_sum(ls, red) * (1.0f / HID);
    float lv = 0.f;
    for (int i = threadIdx.x; i < HID; i += blockDim.x) { float d = sh[i] - mu; lv += d * d; }
    float var = blk_sum(lv, red) * (1.0f / HID);
    float r = rsqrtf(var + 1e-7f);
    long obase = (long)tok * HID;
    for (int i = threadIdx.x; i < HID; i += blockDim.x)
        out[obase + i] = ((sh[i] - mu) * r * s[i] + b[i]) * m;
}

// ---------------- residual + LN: out = LN((res?) + t) -------------------------
__global__ void add_ln_k(const float* res, const float* __restrict__ t,
                         const float* __restrict__ s, const float* __restrict__ b,
                         float* out)
{
    __shared__ float sh[HID];
    __shared__ float red[8];
    long base = (long)blockIdx.x * HID;
    float ls = 0.f;
    for (int i = threadIdx.x; i < HID; i += blockDim.x) {
        float v = t[base + i];
        if (res) v += res[base + i];
        sh[i] = v; ls += v;
    }
    __syncthreads();
    float mu = blk_sum(ls, red) * (1.0f / HID);
    float lv = 0.f;
    for (int i = threadIdx.x; i < HID; i += blockDim.x) { float d = sh[i] - mu; lv += d * d; }
    float var = blk_sum(lv, red) * (1.0f / HID);
    float r = rsqrtf(var + 1e-7f);
    for (int i = threadIdx.x; i < HID; i += blockDim.x)
        out[base + i] = (sh[i] - mu) * r * s[i] + b[i];
}

// ---------------- DeBERTa log-bucket relative index ---------------------------
__global__ void build_idx_k(int* __restrict__ idxm)
{
    int q = blockIdx.x;
    const int mid = 128;
    for (int k = threadIdx.x; k < SEQ; k += blockDim.x) {
        int rel = q - k;
        int a = (rel < mid && rel > -mid) ? (mid - 1) : (rel < 0 ? -rel : rel);
        int bucket;
        if (a <= mid) bucket = rel;
        else {
            float lp = ceilf(logf((float)a / (float)mid) / logf(511.0f / (float)mid) * (float)(mid - 1))
                       + (float)mid;
            float sgn = (rel > 0) ? 1.f : ((rel < 0) ? -1.f : 0.f);
            bucket = (int)(lp * sgn);
        }
        int J = bucket + 256;
        J = J < 0 ? 0 : (J > 511 ? 511 : J);
        idxm[q * SEQ + k] = J;
    }
}

// ------- combine + mask + softmax:  probs = softmax((qk + c2p[J] + p2c[J])/scale)
__global__ void attn_softmax_k(float* __restrict__ sc, const float* __restrict__ c2p,
                               const float* __restrict__ p2c, const int* __restrict__ idxm,
                               const int* __restrict__ am)
{
    __shared__ float red[4];
    int q = blockIdx.x, z = blockIdx.y;
    int b = z >> 4;                     // NHD = 16
    long ro = ((long)z * SEQ + q) * (long)SEQ;
    float* row = sc + ro;
    const float* cr = c2p + ro;
    const float* pb = p2c + (long)z * SEQ * 512;
    int mq = am[b * SEQ + q];
    const float scale = sqrtf(3.0f * (float)HDD);
    float vals[4]; int msk[4];
    float mx = -3.402823466e38f;
    #pragma unroll
    for (int t = 0; t < 4; t++) {
        int k = threadIdx.x + t * 128;
        int J = idxm[q * SEQ + k];
        float v = (row[k] + cr[J] + pb[(long)k * 512 + J]) / scale;
        int mk = mq & am[b * SEQ + k];
        vals[t] = v; msk[t] = mk;
        if (mk) mx = fmaxf(mx, v);
    }
    #pragma unroll
    for (int o = 16; o; o >>= 1) mx = fmaxf(mx, __shfl_down_sync(0xffffffffu, mx, o));
    if ((threadIdx.x & 31) == 0) red[threadIdx.x >> 5] = mx;
    __syncthreads();
    mx = fmaxf(fmaxf(red[0], red[1]), fmaxf(red[2], red[3]));
    float ls = 0.f;
    #pragma unroll
    for (int t = 0; t < 4; t++) {
        float e = msk[t] ? expf(vals[t] - mx) : 0.f;
        vals[t] = e; ls += e;
    }
    __syncthreads();
    #pragma unroll
    for (int o = 16; o; o >>= 1) ls += __shfl_down_sync(0xffffffffu, ls, o);
    if ((threadIdx.x & 31) == 0) red[threadIdx.x >> 5] = ls;
    __syncthreads();
    float sum = red[0] + red[1] + red[2] + red[3];
    float inv = sum > 0.f ? 1.0f / sum : 0.f;
    #pragma unroll
    for (int t = 0; t < 4; t++) row[threadIdx.x + t * 128] = vals[t] * inv;
}

// ---------------- decoder (N=14) + per-row masked NLL -------------------------
__global__ void decoder_k(const float* __restrict__ t, const float* __restrict__ Wd,
                          const float* __restrict__ bd, const int* __restrict__ labels,
                          const int* __restrict__ am, float* __restrict__ out,
                          int logit_limit, float* __restrict__ nll)
{
    __shared__ float sh[HID];
    __shared__ float wred[4][NCL];
    __shared__ float lg[NCL];
    int row = blockIdx.x;
    long base = (long)row * HID;
    for (int i = threadIdx.x; i < HID; i += 128) sh[i] = t[base + i];
    __syncthreads();
    float p[NCL];
    #pragma unroll
    for (int c = 0; c < NCL; c++) p[c] = 0.f;
    for (int i = threadIdx.x; i < HID; i += 128) {
        float tv = sh[i];
        const float* w = Wd + (long)i * NCL;
        #pragma unroll
        for (int c = 0; c < NCL; c++) p[c] = fmaf(tv, w[c], p[c]);
    }
    #pragma unroll
    for (int c = 0; c < NCL; c++)
        #pragma unroll
        for (int o = 16; o; o >>= 1) p[c] += __shfl_down_sync(0xffffffffu, p[c], o);
    if ((threadIdx.x & 31) == 0) {
        int w = threadIdx.x >> 5;
        #pragma unroll
        for (int c = 0; c < NCL; c++) wred[w][c] = p[c];
    }
    __syncthreads();
    if (threadIdx.x < NCL) {
        float v = wred[0][threadIdx.x] + wred[1][threadIdx.x]
                + wred[2][threadIdx.x] + wred[3][threadIdx.x] + bd[threadIdx.x];
        lg[threadIdx.x] = v;
        int oi = row * NCL + threadIdx.x;
        if (oi < logit_limit) out[oi] = v;
    }
    __syncthreads();
    if (threadIdx.x == 0) {
        float m = lg[0];
        #pragma unroll
        for (int c = 1; c < NCL; c++) m = fmaxf(m, lg[c]);
        float ssum = 0.f;
        #pragma unroll
        for (int c = 0; c < NCL; c++) ssum += expf(lg[c] - m);
        float lse = m + logf(ssum);
        float nl = lse - lg[labels[row]];
        nll[row] = nl * (float)am[row];
    }
}

__global__ void finalize_k(const float* __restrict__ nll, const int* __restrict__ am,
                           float* __restrict__ out, int loss_idx)
{
    __shared__ float red[8];
    float a = 0.f, bm = 0.f;
    for (int i = threadIdx.x; i < TOK; i += 256) { a += nll[i]; bm += (float)am[i]; }
    float sa = blk_sum(a, red);
    float sb = blk_sum(bm, red);
    if (threadIdx.x == 0 && loss_idx >= 0) out[loss_idx] = sa / fmaxf(sb, 1.0f);
}

// ------------------------------- host driver ----------------------------------
static inline JobDesc mkjob(const float* A, const float* B, float* C,
                            const float* bias, int M)
{
    JobDesc d; d.A = A; d.B = B; d.C = C; d.bias = bias; d.M = M; d.pad = 0;
    return d;
}

extern "C" void kernel_launch(void* const* d_in, const int* in_sizes, int n_in,
                              void* d_out, int out_size)
{
    (void)in_sizes; (void)n_in;
    const float* word_emb = (const float*)d_in[0];
    const float* emb_ln_s = (const float*)d_in[1];
    const float* emb_ln_b = (const float*)d_in[2];
    const float* rel_emb  = (const float*)d_in[3];
    const float* rel_ln_s = (const float*)d_in[4];
    const float* rel_ln_b = (const float*)d_in[5];
    const float* Wq = (const float*)d_in[6];
    const float* bq = (const float*)d_in[7];
    const float* Wk = (const float*)d_in[8];
    const float* bk = (const float*)d_in[9];
    const float* Wv = (const float*)d_in[10];
    const float* bv = (const float*)d_in[11];
    const float* Wo = (const float*)d_in[12];
    const float* bo = (const float*)d_in[13];
    const float* ln1_s = (const float*)d_in[14];
    const float* ln1_b = (const float*)d_in[15];
    const float* W1 = (const float*)d_in[16];
    const float* b1 = (const float*)d_in[17];
    const float* W2 = (const float*)d_in[18];
    const float* b2 = (const float*)d_in[19];
    const float* ln2_s = (const float*)d_in[20];
    const float* ln2_b = (const float*)d_in[21];
    const float* Wt = (const float*)d_in[22];
    const float* bt = (const float*)d_in[23];
    const float* tln_s = (const float*)d_in[24];
    const float* tln_b = (const float*)d_in[25];
    const float* Wd = (const float*)d_in[26];
    const float* bd = (const float*)d_in[27];
    const int* ids    = (const int*)d_in[28];
    const int* am     = (const int*)d_in[29];
    const int* labels = (const int*)d_in[30];
    float* out = (float*)d_out;

    float *x, *q, *k, *v, *rel, *pk, *pq, *sc, *c2p, *p2c, *ctx, *ff, *nll;
    int* idxm;
    cudaGetSymbolAddress((void**)&x,   g_x);
    cudaGetSymbolAddress((void**)&q,   g_q);
    cudaGetSymbolAddress((void**)&k,   g_k);
    cudaGetSymbolAddress((void**)&v,   g_v);
    cudaGetSymbolAddress((void**)&rel, g_rel);
    cudaGetSymbolAddress((void**)&pk,  g_pk);
    cudaGetSymbolAddress((void**)&pq,  g_pq);
    cudaGetSymbolAddress((void**)&sc,  g_sc);
    cudaGetSymbolAddress((void**)&c2p, g_c2p);
    cudaGetSymbolAddress((void**)&p2c, g_p2c);
    cudaGetSymbolAddress((void**)&ctx, g_ctx);
    cudaGetSymbolAddress((void**)&ff,  g_ff);
    cudaGetSymbolAddress((void**)&nll, g_nll);
    cudaGetSymbolAddress((void**)&idxm, g_idxm);

    // allow 60KB dynamic smem on all GEMM instantiations (idempotent)
    cudaFuncSetAttribute(tgemm_k<0,false,8>,  cudaFuncAttributeMaxDynamicSharedMemorySize, SMEM_BYTES);
    cudaFuncSetAttribute(tgemm_k<1,false,8>,  cudaFuncAttributeMaxDynamicSharedMemorySize, SMEM_BYTES);
    cudaFuncSetAttribute(tgemm_k<0,true,96>,  cudaFuncAttributeMaxDynamicSharedMemorySize, SMEM_BYTES);
    cudaFuncSetAttribute(tgemm_k<0,false,32>, cudaFuncAttributeMaxDynamicSharedMemorySize, SMEM_BYTES);

    build_idx_k<<<SEQ, 128>>>(idxm);
    embed_ln_k<<<TOK, 256>>>(word_emb, emb_ln_s, emb_ln_b, ids, am, x);
    add_ln_k<<<SEQ, 256>>>(nullptr, rel_emb, rel_ln_s, rel_ln_b, rel);

    // -- fixed job tables (same scratch addresses every layer) --
    JobsP<96> scJobs;
    for (int job = 0; job < 3; job++)
        for (int head = 0; head < 32; head++) {
            int b = head >> 4, h = head & 15;
            const float* Aj = (job < 2 ? q : k) + (long)b * SHs + h * HDD;
            const float* Bj;
            if (job == 0)      Bj = k  + (long)b * SHs + h * HDD;
            else if (job == 1) Bj = pk + h * HDD;
            else               Bj = pq + h * HDD;
            float* Cj = (job == 0 ? sc : job == 1 ? c2p : p2c) + (long)head * HSC;
            scJobs.j[job * 32 + head] = mkjob(Aj, Bj, Cj, nullptr, 512);
        }
    JobsP<32> ctxJobs;
    for (int head = 0; head < 32; head++) {
        int b = head >> 4, h = head & 15;
        ctxJobs.j[head] = mkjob(sc + (long)head * HSC,
                                v + (long)b * SHs + h * HDD,
                                ctx + (long)b * SHs + h * HDD, nullptr, 512);
    }

    for (int l = 0; l < NL; l++) {
        const float* Wq_l = Wq + (long)l * HID * HID;
        const float* Wk_l = Wk + (long)l * HID * HID;
        const float* Wv_l = Wv + (long)l * HID * HID;
        const float* Wo_l = Wo + (long)l * HID * HID;
        const float* bq_l = bq + l * HID;
        const float* bk_l = bk + l * HID;
        const float* bv_l = bv + l * HID;
        const float* bo_l = bo + l * HID;
        const float* W1_l = W1 + (long)l * HID * FFD;
        const float* b1_l = b1 + l * FFD;
        const float* W2_l = W2 + (long)l * FFD * HID;
        const float* b2_l = b2 + l * HID;

        // fused Q/K/V projections + positional K/Q (share_att_key)
        JobsP<8> pj;
        pj.j[0] = mkjob(x,   Wq_l, q,  bq_l, 1024);
        pj.j[1] = mkjob(x,   Wk_l, k,  bk_l, 1024);
        pj.j[2] = mkjob(x,   Wv_l, v,  bv_l, 1024);
        pj.j[3] = mkjob(rel, Wk_l, pk, bk_l, 512);
        pj.j[4] = mkjob(rel, Wq_l, pq, bq_l, 512);
        tgemm_k<0,false,8><<<dim3(16,8,5), 256, SMEM_BYTES>>>(pj, HID, HID, HID, HID);

        // fused attention GEMMs: qk, c2p, p2c  (A @ B^T per (b,h))
        tgemm_k<0,true,96><<<dim3(8,4,96), 256, SMEM_BYTES>>>(scJobs, HDD, HID, HID, 512);

        // combine disentangled biases + mask + softmax (in-place -> probs)
        attn_softmax_k<<<dim3(SEQ, BSZ * NHD), 128>>>(sc, c2p, p2c, idxm, am);

        // ctx = probs @ V (per head)
        tgemm_k<0,false,32><<<dim3(1,4,32), 256, SMEM_BYTES>>>(ctxJobs, SEQ, 512, HID, HID);

        // output proj + residual LN
        JobsP<8> oj; oj.j[0] = mkjob(ctx, Wo_l, ff, bo_l, 1024);
        tgemm_k<0,false,8><<<dim3(16,8,1), 256, SMEM_BYTES>>>(oj, HID, HID, HID, HID);
        add_ln_k<<<TOK, 256>>>(x, ff, ln1_s + l * HID, ln1_b + l * HID, x);

        // FFN
        JobsP<8> f1; f1.j[0] = mkjob(x, W1_l, ff, b1_l, 1024);
        tgemm_k<1,false,8><<<dim3(64,8,1), 256, SMEM_BYTES>>>(f1, HID, HID, FFD, FFD);
        JobsP<8> f2; f2.j[0] = mkjob(ff, W2_l, ctx, b2_l, 1024);
        tgemm_k<0,false,8><<<dim3(16,8,1), 256, SMEM_BYTES>>>(f2, FFD, FFD, HID, HID);
        add_ln_k<<<TOK, 256>>>(x, ctx, ln2_s + l * HID, ln2_b + l * HID, x);
    }

    // transform head: LN(gelu(x @ Wt + bt))
    JobsP<8> tj; tj.j[0] = mkjob(x, Wt, ff, bt, 1024);
    tgemm_k<1,false,8><<<dim3(16,8,1), 256, SMEM_BYTES>>>(tj, HID, HID, HID, HID);
    add_ln_k<<<TOK, 256>>>(nullptr, ff, tln_s, tln_b, q);   // reuse q buffer as t

    int logits_n = TOK * NCL;                               // 14336
    int logit_limit = (out_size > 1) ? (out_size < logits_n ? out_size : logits_n) : 0;
    int loss_idx = (out_size == 1) ? 0 : (out_size > logits_n ? logits_n : -1);
    decoder_k<<<TOK, 128>>>(q, Wd, bd, labels, am, out, logit_limit, nll);
    finalize_k<<<1, 256>>>(nll, am, out, loss_idx);
}